// round 14
// baseline (speedup 1.0000x reference)
#include <cuda_runtime.h>
#include <cuda_bf16.h>
#include <math.h>
#include <stdint.h>

// ---------------- problem constants ----------------
#define TOK    25088      // 8*56*56
#define NBATCH 8
#define HWDIM  56
#define CDIM   256
#define QKC    768        // qkv width
#define HIDC   1024
#define NWIN   49         // 7*7 windows per image
#define NPALL  392        // 8*49
#define WSCALE 0.0625f    // 256^-0.5

// ---------------- scratch (device globals; no allocs allowed) ----------------
__device__ __align__(256) float g_tmp256[TOK * CDIM];   // ln1(bf16) / lepe(f32) / ln2(bf16)
__device__ __align__(256) float g_qkv[TOK * QKC];
__device__ __align__(256) float g_x1[TOK * CDIM];
__device__ __align__(256) float g_hid[(size_t)TOK * HIDC / 2];  // bf16 (attn-out, then mlp hid)
__device__ float g_qwin[NPALL * CDIM];
__device__ float g_kwin[NPALL * CDIM];
__device__ int   g_topk[NPALL * 4];
__device__ __align__(256) __nv_bfloat16 g_wbf[786432];  // transposed bf16 weights

#define WT_QKV 0
#define WT_WO  196608
#define WT_W1  262144
#define WT_W2  524288

__device__ __forceinline__ uint32_t f2tf32(float x) {
    uint32_t u;
    asm("cvt.rna.tf32.f32 %0, %1;" : "=r"(u) : "f"(x));
    return u;
}
__device__ __forceinline__ float tf32f(float x) { return __uint_as_float(f2tf32(x)); }

__device__ __forceinline__ uint32_t smem_u32(const void* p) {
    uint32_t a;
    asm("{ .reg .u64 t; cvta.to.shared.u64 t, %1; cvt.u32.u64 %0, t; }" : "=r"(a) : "l"(p));
    return a;
}
__device__ __forceinline__ void cpasync16(uint32_t s, const void* g) {
    asm volatile("cp.async.cg.shared.global [%0], [%1], 16;" :: "r"(s), "l"(g) : "memory");
}
#define CP_COMMIT() asm volatile("cp.async.commit_group;" ::: "memory")
#define CP_WAIT0()  asm volatile("cp.async.wait_group 0;" ::: "memory")

// ---------------- merged weight transpose + bf16 convert (all 4 weights) --------------
__global__ void wtrans_all_kernel(const float* __restrict__ qkv_w, const float* __restrict__ wo_w,
                                  const float* __restrict__ w1, const float* __restrict__ w2,
                                  __nv_bfloat16* __restrict__ wbf) {
    __shared__ float tile[32][33];
    int b = blockIdx.x;
    const float* W; __nv_bfloat16* WT; int K, N, t;
    if (b < 192)      { W = qkv_w; WT = wbf + WT_QKV; K = CDIM; N = QKC;  t = b; }
    else if (b < 256) { W = wo_w;  WT = wbf + WT_WO;  K = CDIM; N = CDIM; t = b - 192; }
    else if (b < 512) { W = w1;    WT = wbf + WT_W1;  K = CDIM; N = HIDC; t = b - 256; }
    else              { W = w2;    WT = wbf + WT_W2;  K = HIDC; N = CDIM; t = b - 512; }
    int ktiles = K >> 5;
    int k0 = (t % ktiles) * 32, n0 = (t / ktiles) * 32;
    int tx = threadIdx.x & 31, ty = threadIdx.x >> 5;   // 32 x 8
    #pragma unroll
    for (int i = ty; i < 32; i += 8)
        tile[i][tx] = W[(size_t)(k0 + i) * N + n0 + tx];
    __syncthreads();
    #pragma unroll
    for (int i = ty; i < 32; i += 8)
        WT[(size_t)(n0 + i) * K + k0 + tx] = __float2bfloat16(tile[tx][i]);
}

// ---------------- LayerNorm (warp per token) -> bf16 out, optional window permute ----
template<bool PERM>
__global__ void ln_kernel(const float* __restrict__ X, const float* __restrict__ gam,
                          const float* __restrict__ bet, __nv_bfloat16* __restrict__ Y) {
    int warp = threadIdx.x >> 5, lane = threadIdx.x & 31;
    int t = blockIdx.x * 8 + warp;
    const float* row = X + (size_t)t * CDIM;
    float4 v0 = *(const float4*)(row + lane * 8);
    float4 v1 = *(const float4*)(row + lane * 8 + 4);
    float s  = v0.x + v0.y + v0.z + v0.w + v1.x + v1.y + v1.z + v1.w;
    float sq = v0.x*v0.x + v0.y*v0.y + v0.z*v0.z + v0.w*v0.w
             + v1.x*v1.x + v1.y*v1.y + v1.z*v1.z + v1.w*v1.w;
    #pragma unroll
    for (int o = 16; o; o >>= 1) {
        s  += __shfl_xor_sync(0xffffffffu, s, o);
        sq += __shfl_xor_sync(0xffffffffu, sq, o);
    }
    float mu  = s * (1.0f / 256.0f);
    float var = sq * (1.0f / 256.0f) - mu * mu;
    float inv = rsqrtf(var + 1e-6f);

    int orow;
    if (PERM) {
        int n = t / 3136, rem = t % 3136;
        int y = rem / 56, x = rem % 56;
        int p  = (y >> 3) * 7 + (x >> 3);
        int qi = (y & 7) * 8 + (x & 7);
        orow = (n * NWIN + p) * 64 + qi;
    } else {
        orow = t;
    }
    float4 g0 = *(const float4*)(gam + lane * 8);
    float4 g1 = *(const float4*)(gam + lane * 8 + 4);
    float4 b0 = *(const float4*)(bet + lane * 8);
    float4 b1 = *(const float4*)(bet + lane * 8 + 4);
    __nv_bfloat162 o0 = __floats2bfloat162_rn((v0.x - mu) * inv * g0.x + b0.x,
                                              (v0.y - mu) * inv * g0.y + b0.y);
    __nv_bfloat162 o1 = __floats2bfloat162_rn((v0.z - mu) * inv * g0.z + b0.z,
                                              (v0.w - mu) * inv * g0.w + b0.w);
    __nv_bfloat162 o2 = __floats2bfloat162_rn((v1.x - mu) * inv * g1.x + b1.x,
                                              (v1.y - mu) * inv * g1.y + b1.y);
    __nv_bfloat162 o3 = __floats2bfloat162_rn((v1.z - mu) * inv * g1.z + b1.z,
                                              (v1.w - mu) * inv * g1.w + b1.w);
    uint4 pk;
    pk.x = *(uint32_t*)&o0; pk.y = *(uint32_t*)&o1;
    pk.z = *(uint32_t*)&o2; pk.w = *(uint32_t*)&o3;
    *(uint4*)(Y + (size_t)orow * CDIM + lane * 8) = pk;
}

// ---------------- BF16 tensor-core GEMM 128x128x32, 256 threads, cp.async staged ------
__device__ __forceinline__ float gelu_exact(float x) {
    return 0.5f * x * (1.0f + erff(x * 0.70710678118654752440f));
}

#define WPAD 20   // row stride in 32-bit words (bf16 pairs); 16 data + 4 pad

template<int EPI, int ABF, int DOMEAN>
__global__ __launch_bounds__(256)
void tgemm_kernel(const void* __restrict__ Ain, const __nv_bfloat16* __restrict__ WT,
                  const float* __restrict__ bias, const float* __restrict__ R,
                  void* __restrict__ Cout, float* __restrict__ qw, float* __restrict__ kw,
                  int M, int N, int K) {
    __shared__ uint32_t sA[2][128 * WPAD];
    __shared__ uint32_t sB[2][128 * WPAD];

    int tid = threadIdx.x;
    int warp = tid >> 5, lane = tid & 31;
    int qr = lane >> 2, qc = lane & 3;
    int warp_m = warp >> 2, warp_n = warp & 3;   // 2 x 4
    int m0 = blockIdx.y * 128, n0 = blockIdx.x * 128;

    int aRow = tid >> 1, half = tid & 1;
    const __nv_bfloat16* Bg = WT + (size_t)(n0 + aRow) * K + half * 16;
    const __nv_bfloat16* Agb = (const __nv_bfloat16*)Ain + (size_t)(m0 + aRow) * K + half * 16;
    const float*         Agf = (const float*)Ain + (size_t)(m0 + aRow) * K + half * 16;
    uint32_t dstOff = (uint32_t)(aRow * WPAD + half * 8) * 4u;
    uint32_t sAb = smem_u32(&sA[0][0]);
    uint32_t sBb = smem_u32(&sB[0][0]);
    const uint32_t BUFB = 128u * WPAD * 4u;

    float acc[4][4][4];
    #pragma unroll
    for (int i = 0; i < 4; i++)
        #pragma unroll
        for (int j = 0; j < 4; j++)
            #pragma unroll
            for (int v = 0; v < 4; v++) acc[i][j][v] = 0.0f;

    int nch = K >> 5;

    if (ABF) {
        cpasync16(sAb + dstOff, Agb);
        cpasync16(sAb + dstOff + 16, Agb + 8);
    } else {
        float4 a0 = *(const float4*)(Agf);
        float4 a1 = *(const float4*)(Agf + 4);
        float4 a2 = *(const float4*)(Agf + 8);
        float4 a3 = *(const float4*)(Agf + 12);
        uint32_t* dA = &sA[0][aRow * WPAD + half * 8];
        __nv_bfloat162 h;
        h = __floats2bfloat162_rn(a0.x, a0.y); dA[0] = *(uint32_t*)&h;
        h = __floats2bfloat162_rn(a0.z, a0.w); dA[1] = *(uint32_t*)&h;
        h = __floats2bfloat162_rn(a1.x, a1.y); dA[2] = *(uint32_t*)&h;
        h = __floats2bfloat162_rn(a1.z, a1.w); dA[3] = *(uint32_t*)&h;
        h = __floats2bfloat162_rn(a2.x, a2.y); dA[4] = *(uint32_t*)&h;
        h = __floats2bfloat162_rn(a2.z, a2.w); dA[5] = *(uint32_t*)&h;
        h = __floats2bfloat162_rn(a3.x, a3.y); dA[6] = *(uint32_t*)&h;
        h = __floats2bfloat162_rn(a3.z, a3.w); dA[7] = *(uint32_t*)&h;
    }
    cpasync16(sBb + dstOff, Bg);
    cpasync16(sBb + dstOff + 16, Bg + 8);
    CP_COMMIT();
    CP_WAIT0();
    __syncthreads();

    for (int i = 0; i < nch; i++) {
        int b = i & 1;
        bool more = (i + 1) < nch;
        float4 na0, na1, na2, na3;
        if (more) {
            uint32_t off = (uint32_t)(b ^ 1) * BUFB + dstOff;
            if (ABF) {
                const __nv_bfloat16* ag = Agb + (size_t)(i + 1) * 32;
                cpasync16(sAb + off, ag);
                cpasync16(sAb + off + 16, ag + 8);
            } else {
                const float* ag = Agf + (size_t)(i + 1) * 32;
                na0 = *(const float4*)(ag);
                na1 = *(const float4*)(ag + 4);
                na2 = *(const float4*)(ag + 8);
                na3 = *(const float4*)(ag + 12);
            }
            const __nv_bfloat16* bg = Bg + (size_t)(i + 1) * 32;
            cpasync16(sBb + off, bg);
            cpasync16(sBb + off + 16, bg + 8);
            CP_COMMIT();
        }

        const uint32_t* Ab = sA[b];
        const uint32_t* Bb = sB[b];
        #pragma unroll
        for (int ksp = 0; ksp < 2; ksp++) {
            uint32_t af[4][4], bf[4][2];
            #pragma unroll
            for (int mt = 0; mt < 4; mt++) {
                int r = warp_m * 64 + mt * 16 + qr;
                af[mt][0] = Ab[(r)     * WPAD + ksp * 8 + qc];
                af[mt][1] = Ab[(r + 8) * WPAD + ksp * 8 + qc];
                af[mt][2] = Ab[(r)     * WPAD + ksp * 8 + qc + 4];
                af[mt][3] = Ab[(r + 8) * WPAD + ksp * 8 + qc + 4];
            }
            #pragma unroll
            for (int nt = 0; nt < 4; nt++) {
                int cn = warp_n * 32 + nt * 8 + qr;
                bf[nt][0] = Bb[cn * WPAD + ksp * 8 + qc];
                bf[nt][1] = Bb[cn * WPAD + ksp * 8 + qc + 4];
            }
            #pragma unroll
            for (int mt = 0; mt < 4; mt++)
                #pragma unroll
                for (int nt = 0; nt < 4; nt++) {
                    asm volatile(
                        "mma.sync.aligned.m16n8k16.row.col.f32.bf16.bf16.f32 "
                        "{%0,%1,%2,%3}, {%4,%5,%6,%7}, {%8,%9}, {%0,%1,%2,%3};"
                        : "+f"(acc[mt][nt][0]), "+f"(acc[mt][nt][1]),
                          "+f"(acc[mt][nt][2]), "+f"(acc[mt][nt][3])
                        : "r"(af[mt][0]), "r"(af[mt][1]), "r"(af[mt][2]), "r"(af[mt][3]),
                          "r"(bf[nt][0]), "r"(bf[nt][1]));
                }
        }

        if (more) {
            if (!ABF) {
                uint32_t* dA = &sA[b ^ 1][aRow * WPAD + half * 8];
                __nv_bfloat162 h;
                h = __floats2bfloat162_rn(na0.x, na0.y); dA[0] = *(uint32_t*)&h;
                h = __floats2bfloat162_rn(na0.z, na0.w); dA[1] = *(uint32_t*)&h;
                h = __floats2bfloat162_rn(na1.x, na1.y); dA[2] = *(uint32_t*)&h;
                h = __floats2bfloat162_rn(na1.z, na1.w); dA[3] = *(uint32_t*)&h;
                h = __floats2bfloat162_rn(na2.x, na2.y); dA[4] = *(uint32_t*)&h;
                h = __floats2bfloat162_rn(na2.z, na2.w); dA[5] = *(uint32_t*)&h;
                h = __floats2bfloat162_rn(na3.x, na3.y); dA[6] = *(uint32_t*)&h;
                h = __floats2bfloat162_rn(na3.z, na3.w); dA[7] = *(uint32_t*)&h;
            }
            CP_WAIT0();
        }
        __syncthreads();
    }

    // ---- epilogue ----
    #pragma unroll
    for (int nt = 0; nt < 4; nt++) {
        int col = n0 + warp_n * 32 + nt * 8 + qc * 2;
        float bx = bias[col], by = bias[col + 1];
        float cs0 = 0.f, cs1 = 0.f;
        #pragma unroll
        for (int mt = 0; mt < 4; mt++) {
            int row = m0 + warp_m * 64 + mt * 16 + qr;
            float v0 = acc[mt][nt][0] + bx;
            float v1 = acc[mt][nt][1] + by;
            float v2 = acc[mt][nt][2] + bx;
            float v3 = acc[mt][nt][3] + by;
            if (DOMEAN) { cs0 += v0 + v2; cs1 += v1 + v3; }
            if (EPI == 1) {
                __nv_bfloat162 ha = __floats2bfloat162_rn(gelu_exact(v0), gelu_exact(v1));
                __nv_bfloat162 hb = __floats2bfloat162_rn(gelu_exact(v2), gelu_exact(v3));
                __nv_bfloat16* cb = (__nv_bfloat16*)Cout;
                *(__nv_bfloat162*)(cb + (size_t)row * N + col)       = ha;
                *(__nv_bfloat162*)(cb + (size_t)(row + 8) * N + col) = hb;
            } else {
                if (EPI == 2) {
                    float2 ra = *(const float2*)(R + (size_t)row * N + col);
                    float2 rb = *(const float2*)(R + (size_t)(row + 8) * N + col);
                    v0 += ra.x; v1 += ra.y; v2 += rb.x; v3 += rb.y;
                }
                float* cf = (float*)Cout;
                float2 oa; oa.x = v0; oa.y = v1;
                float2 ob; ob.x = v2; ob.y = v3;
                *(float2*)(cf + (size_t)row * N + col)       = oa;
                *(float2*)(cf + (size_t)(row + 8) * N + col) = ob;
            }
        }
        if (DOMEAN && n0 < 512) {
            #pragma unroll
            for (int o = 4; o <= 16; o <<= 1) {
                cs0 += __shfl_xor_sync(0xffffffffu, cs0, o);
                cs1 += __shfl_xor_sync(0xffffffffu, cs1, o);
            }
            if (qr == 0) {
                int win = blockIdx.y * 2 + warp_m;
                float mv0 = cs0 * (1.0f / 64.0f);
                float mv1 = cs1 * (1.0f / 64.0f);
                if (col < 256) {
                    qw[win * CDIM + col]     = mv0;
                    qw[win * CDIM + col + 1] = mv1;
                } else {
                    kw[win * CDIM + col - 256] = mv0;
                    kw[win * CDIM + col - 255] = mv1;
                }
            }
        }
    }
}

// ---------------- router v2: one block per image, smem-staged, 8 warps ----------------
// dynamic smem: qs[49*260] + ks[49*260] floats (~102 KB)
#define RPAD 260
__global__ void router_kernel(const float* __restrict__ qw, const float* __restrict__ kw,
                              int* __restrict__ topk) {
    extern __shared__ float rsm[];
    float* qs = rsm;                  // [49][RPAD], pre-scaled
    float* ks = rsm + NWIN * RPAD;    // [49][RPAD]
    __shared__ float lgbuf[8][NWIN];

    int n = blockIdx.x;
    int tid = threadIdx.x, warp = tid >> 5, lane = tid & 31;

    for (int i = tid; i < NWIN * CDIM; i += 256) {
        int r = i >> 8, c = i & 255;
        qs[r * RPAD + c] = qw[(size_t)(n * NWIN + r) * CDIM + c] * WSCALE;
        ks[r * RPAD + c] = kw[(size_t)(n * NWIN + r) * CDIM + c];
    }
    __syncthreads();

    for (int p = warp; p < NWIN; p += 8) {
        // lane computes logits for q = lane and q = lane + 32 (if < 49)
        float s0 = 0.f, s1 = 0.f;
        const float* qrow = qs + p * RPAD;
        const float* k1 = ks + lane * RPAD;
        const float* k2 = ks + (lane + 32) * RPAD;
        bool has2 = (lane + 32) < NWIN;
        #pragma unroll 8
        for (int c = 0; c < CDIM; c += 4) {
            float4 qv = *(const float4*)(qrow + c);
            float4 kv1 = *(const float4*)(k1 + c);
            s0 += qv.x * kv1.x + qv.y * kv1.y + qv.z * kv1.z + qv.w * kv1.w;
            if (has2) {
                float4 kv2 = *(const float4*)(k2 + c);
                s1 += qv.x * kv2.x + qv.y * kv2.y + qv.z * kv2.z + qv.w * kv2.w;
            }
        }
        if (lane < NWIN) lgbuf[warp][lane] = s0;
        if (has2) lgbuf[warp][lane + 32] = s1;
        __syncwarp();
        if (lane == 0) {
            bool used[NWIN];
            #pragma unroll
            for (int i = 0; i < NWIN; i++) used[i] = false;
            int* dst = topk + (size_t)(n * NWIN + p) * 4;
            for (int r = 0; r < 4; r++) {
                float best = -1e30f; int bi = 0;
                for (int q = 0; q < NWIN; q++)
                    if (!used[q] && lgbuf[warp][q] > best) { best = lgbuf[warp][q]; bi = q; }
                used[bi] = true;
                dst[r] = bi;
            }
        }
        __syncwarp();
    }
}

// ---------------- 5x5 depthwise lepe, smem-tiled, WRITES O (first writer) ------------
__global__ __launch_bounds__(256)
void lepe_kernel(const float* __restrict__ QKV, const float* __restrict__ W,
                 const float* __restrict__ B, float* __restrict__ O) {
    __shared__ float sv[144][64];
    __shared__ float sw[25][64];
    int np = blockIdx.x, cg = blockIdx.y;
    int n = np / NWIN, p = np % NWIN;
    int jj = p / 7, ii = p % 7;
    int tid = threadIdx.x;

    for (int i = tid; i < 1600; i += 256)
        sw[i / 64][i % 64] = W[(i / 64) * CDIM + cg * 64 + (i % 64)];

    for (int i = tid; i < 2304; i += 256) {
        int pos = i >> 4, c4 = i & 15;
        int yy = jj * 8 + (pos / 12) - 2;
        int xx = ii * 8 + (pos % 12) - 2;
        float4 v = make_float4(0.f, 0.f, 0.f, 0.f);
        if (yy >= 0 && yy < HWDIM && xx >= 0 && xx < HWDIM) {
            int pp = (yy >> 3) * 7 + (xx >> 3);
            int qi = (yy & 7) * 8 + (xx & 7);
            const float* src = QKV + ((size_t)(n * NWIN + pp) * 64 + qi) * QKC + 512 + cg * 64;
            v = *(const float4*)(src + c4 * 4);
        }
        *(float4*)&sv[pos][c4 * 4] = v;
    }
    __syncthreads();

    int c = tid & 63, pp0 = tid >> 6;
    float wr[25];
    #pragma unroll
    for (int t5 = 0; t5 < 25; t5++) wr[t5] = sw[t5][c];
    float bias = B[cg * 64 + c];

    #pragma unroll
    for (int hi = 0; hi < 2; hi++) {
        int hh = pp0 + hi * 4;
        #pragma unroll
        for (int ww = 0; ww < 8; ww++) {
            float acc = bias;
            #pragma unroll
            for (int dy = 0; dy < 5; dy++)
                #pragma unroll
                for (int dx = 0; dx < 5; dx++)
                    acc += sv[(hh + dy) * 12 + (ww + dx)][c] * wr[dy * 5 + dx];
            int y = jj * 8 + hh, x = ii * 8 + ww;
            int t = (n * HWDIM + y) * HWDIM + x;
            O[(size_t)t * CDIM + cg * 64 + c] = acc;
        }
    }
}

// ---------------- tensor-core gathered attention (128 thr, 4 warps x 16 rows) --------
// adds lepe (from L), writes bf16 image-order output
#define KS_STRIDE 36
#define VS_STRIDE 40
#define PS_STRIDE 68
__global__ __launch_bounds__(128)
void attn_kernel(const float* __restrict__ QKV, const int* __restrict__ topk,
                 const float* __restrict__ L, __nv_bfloat16* __restrict__ O) {
    __shared__ float ks[64][KS_STRIDE];
    __shared__ float vs[64][VS_STRIDE];
    __shared__ float ps[64][PS_STRIDE];   // Q stage (32 cols), then per-warp P (64 cols)

    int np = blockIdx.x, mh = blockIdx.y;
    int n = np / NWIN, p = np % NWIN;
    int tid = threadIdx.x, warp = tid >> 5, lane = tid & 31;
    int qr = lane >> 2, qc = lane & 3;
    int rbase = warp * 16;               // this warp owns query rows [rbase, rbase+16)

    const float* qbase = QKV + (size_t)np * 64 * QKC + mh * 32;
    for (int i = tid; i < 512; i += 128) {
        int r = i >> 3, c = (i & 7) * 4;
        float4 v = *(const float4*)(qbase + (size_t)r * QKC + c);
        ps[r][c + 0] = tf32f(v.x * WSCALE);
        ps[r][c + 1] = tf32f(v.y * WSCALE);
        ps[r][c + 2] = tf32f(v.z * WSCALE);
        ps[r][c + 3] = tf32f(v.w * WSCALE);
    }
    __syncthreads();

    uint32_t qf[4][4];
    #pragma unroll
    for (int kk = 0; kk < 4; kk++) {
        qf[kk][0] = __float_as_uint(ps[rbase + qr][kk * 8 + qc]);
        qf[kk][1] = __float_as_uint(ps[rbase + qr + 8][kk * 8 + qc]);
        qf[kk][2] = __float_as_uint(ps[rbase + qr][kk * 8 + qc + 4]);
        qf[kk][3] = __float_as_uint(ps[rbase + qr + 8][kk * 8 + qc + 4]);
    }
    __syncthreads();   // ps reused for P below

    float mrun[2] = {-1e30f, -1e30f};
    float lrun[2] = {0.f, 0.f};
    float oacc[4][4];
    #pragma unroll
    for (int nt = 0; nt < 4; nt++)
        #pragma unroll
        for (int v = 0; v < 4; v++) oacc[nt][v] = 0.f;

    for (int t4 = 0; t4 < 4; t4++) {
        int rwin = topk[np * 4 + t4];
        const float* kb = QKV + (size_t)(n * NWIN + rwin) * 64 * QKC + 256 + mh * 32;
        for (int i = tid; i < 512; i += 128) {
            int r = i >> 3, c = (i & 7) * 4;
            float4 kv = *(const float4*)(kb + (size_t)r * QKC + c);
            ks[r][c + 0] = tf32f(kv.x); ks[r][c + 1] = tf32f(kv.y);
            ks[r][c + 2] = tf32f(kv.z); ks[r][c + 3] = tf32f(kv.w);
            float4 vv = *(const float4*)(kb + (size_t)r * QKC + 256 + c);
            vs[r][c + 0] = tf32f(vv.x); vs[r][c + 1] = tf32f(vv.y);
            vs[r][c + 2] = tf32f(vv.z); vs[r][c + 3] = tf32f(vv.w);
        }
        __syncthreads();

        float sacc[8][4];
        #pragma unroll
        for (int nt = 0; nt < 8; nt++)
            #pragma unroll
            for (int v = 0; v < 4; v++) sacc[nt][v] = 0.f;

        #pragma unroll
        for (int kk = 0; kk < 4; kk++) {
            uint32_t bf[8][2];
            #pragma unroll
            for (int nt = 0; nt < 8; nt++) {
                bf[nt][0] = __float_as_uint(ks[nt * 8 + qr][kk * 8 + qc]);
                bf[nt][1] = __float_as_uint(ks[nt * 8 + qr][kk * 8 + qc + 4]);
            }
            #pragma unroll
            for (int nt = 0; nt < 8; nt++) {
                asm volatile(
                    "mma.sync.aligned.m16n8k8.row.col.f32.tf32.tf32.f32 "
                    "{%0,%1,%2,%3}, {%4,%5,%6,%7}, {%8,%9}, {%0,%1,%2,%3};"
                    : "+f"(sacc[nt][0]), "+f"(sacc[nt][1]),
                      "+f"(sacc[nt][2]), "+f"(sacc[nt][3])
                    : "r"(qf[kk][0]), "r"(qf[kk][1]), "r"(qf[kk][2]), "r"(qf[kk][3]),
                      "r"(bf[nt][0]), "r"(bf[nt][1]));
            }
        }

        float rmax[2] = {-1e30f, -1e30f};
        #pragma unroll
        for (int nt = 0; nt < 8; nt++) {
            rmax[0] = fmaxf(rmax[0], fmaxf(sacc[nt][0], sacc[nt][1]));
            rmax[1] = fmaxf(rmax[1], fmaxf(sacc[nt][2], sacc[nt][3]));
        }
        #pragma unroll
        for (int g = 0; g < 2; g++) {
            rmax[g] = fmaxf(rmax[g], __shfl_xor_sync(0xffffffffu, rmax[g], 1));
            rmax[g] = fmaxf(rmax[g], __shfl_xor_sync(0xffffffffu, rmax[g], 2));
        }
        float corr[2], mnew[2];
        #pragma unroll
        for (int g = 0; g < 2; g++) {
            mnew[g] = fmaxf(mrun[g], rmax[g]);
            corr[g] = __expf(mrun[g] - mnew[g]);
            lrun[g] *= corr[g];
            mrun[g] = mnew[g];
        }
        #pragma unroll
        for (int nt = 0; nt < 4; nt++) {
            oacc[nt][0] *= corr[0];
            oacc[nt][1] *= corr[0];
            oacc[nt][2] *= corr[1];
            oacc[nt][3] *= corr[1];
        }
        float psum[2] = {0.f, 0.f};
        {
            int r0 = rbase + qr;
            #pragma unroll
            for (int nt = 0; nt < 8; nt++) {
                float p0 = __expf(sacc[nt][0] - mnew[0]);
                float p1 = __expf(sacc[nt][1] - mnew[0]);
                float p2 = __expf(sacc[nt][2] - mnew[1]);
                float p3 = __expf(sacc[nt][3] - mnew[1]);
                psum[0] += p0 + p1;
                psum[1] += p2 + p3;
                float2 w0; w0.x = tf32f(p0); w0.y = tf32f(p1);
                float2 w1; w1.x = tf32f(p2); w1.y = tf32f(p3);
                *(float2*)&ps[r0][nt * 8 + qc * 2]     = w0;
                *(float2*)&ps[r0 + 8][nt * 8 + qc * 2] = w1;
            }
        }
        #pragma unroll
        for (int g = 0; g < 2; g++) {
            psum[g] += __shfl_xor_sync(0xffffffffu, psum[g], 1);
            psum[g] += __shfl_xor_sync(0xffffffffu, psum[g], 2);
            lrun[g] += psum[g];
        }
        __syncwarp();

        #pragma unroll
        for (int kt = 0; kt < 8; kt++) {
            uint32_t af[4], bf[4][2];
            {
                int r = rbase + qr;
                af[0] = __float_as_uint(ps[r][kt * 8 + qc]);
                af[1] = __float_as_uint(ps[r + 8][kt * 8 + qc]);
                af[2] = __float_as_uint(ps[r][kt * 8 + qc + 4]);
                af[3] = __float_as_uint(ps[r + 8][kt * 8 + qc + 4]);
            }
            #pragma unroll
            for (int nt = 0; nt < 4; nt++) {
                bf[nt][0] = __float_as_uint(vs[kt * 8 + qc][nt * 8 + qr]);
                bf[nt][1] = __float_as_uint(vs[kt * 8 + qc + 4][nt * 8 + qr]);
            }
            #pragma unroll
            for (int nt = 0; nt < 4; nt++) {
                asm volatile(
                    "mma.sync.aligned.m16n8k8.row.col.f32.tf32.tf32.f32 "
                    "{%0,%1,%2,%3}, {%4,%5,%6,%7}, {%8,%9}, {%0,%1,%2,%3};"
                    : "+f"(oacc[nt][0]), "+f"(oacc[nt][1]),
                      "+f"(oacc[nt][2]), "+f"(oacc[nt][3])
                    : "r"(af[0]), "r"(af[1]), "r"(af[2]), "r"(af[3]),
                      "r"(bf[nt][0]), "r"(bf[nt][1]));
            }
        }
        __syncthreads();
    }

    // ---- finalize: /l, add lepe value (fp32), write bf16 image-order output ----
    float linv[2];
    linv[0] = 1.0f / lrun[0];
    linv[1] = 1.0f / lrun[1];

    int jj = p / 7, ii = p % 7;
    #pragma unroll
    for (int half = 0; half < 2; half++) {
        int q = rbase + qr + half * 8;
        int y = jj * 8 + (q >> 3), x = ii * 8 + (q & 7);
        size_t base = ((size_t)(n * HWDIM + y) * HWDIM + x) * CDIM + mh * 32;
        const float* lrow = L + base;
        __nv_bfloat16* orow = O + base;
        float li = linv[half];
        #pragma unroll
        for (int nt = 0; nt < 4; nt++) {
            float2 lv = *(const float2*)(lrow + nt * 8 + qc * 2);
            float a0 = oacc[nt][half * 2 + 0] * li + lv.x;
            float a1 = oacc[nt][half * 2 + 1] * li + lv.y;
            __nv_bfloat162 ov = __floats2bfloat162_rn(a0, a1);
            *(__nv_bfloat162*)(orow + nt * 8 + qc * 2) = ov;
        }
    }
}

// ---------------- host launch ----------------
extern "C" void kernel_launch(void* const* d_in, const int* in_sizes, int n_in,
                              void* d_out, int out_size) {
    const float* x      = (const float*)d_in[0];
    const float* ln1_g  = (const float*)d_in[1];
    const float* ln1_b  = (const float*)d_in[2];
    const float* qkv_w  = (const float*)d_in[3];
    const float* qkv_b  = (const float*)d_in[4];
    const float* lepe_w = (const float*)d_in[5];
    const float* lepe_b = (const float*)d_in[6];
    const float* wo_w   = (const float*)d_in[7];
    const float* wo_b   = (const float*)d_in[8];
    const float* ln2_g  = (const float*)d_in[9];
    const float* ln2_b  = (const float*)d_in[10];
    const float* mlp_w1 = (const float*)d_in[11];
    const float* mlp_b1 = (const float*)d_in[12];
    const float* mlp_w2 = (const float*)d_in[13];
    const float* mlp_b2 = (const float*)d_in[14];
    float* out = (float*)d_out;

    float *tmp, *qkv, *x1, *hid, *qw, *kw;
    int* tk;
    __nv_bfloat16* wbf;
    cudaGetSymbolAddress((void**)&tmp, g_tmp256);
    cudaGetSymbolAddress((void**)&qkv, g_qkv);
    cudaGetSymbolAddress((void**)&x1,  g_x1);
    cudaGetSymbolAddress((void**)&hid, g_hid);
    cudaGetSymbolAddress((void**)&qw,  g_qwin);
    cudaGetSymbolAddress((void**)&kw,  g_kwin);
    cudaGetSymbolAddress((void**)&tk,  g_topk);
    cudaGetSymbolAddress((void**)&wbf, g_wbf);
    __nv_bfloat16* tmpb = (__nv_bfloat16*)tmp;
    __nv_bfloat16* hidb = (__nv_bfloat16*)hid;

    int rsm_bytes = 2 * NWIN * RPAD * sizeof(float);   // ~102 KB
    cudaFuncSetAttribute(router_kernel, cudaFuncAttributeMaxDynamicSharedMemorySize, rsm_bytes);

    // 1. transpose + bf16-convert ALL weights (single launch)
    wtrans_all_kernel<<<768, 256>>>(qkv_w, wo_w, mlp_w1, mlp_w2, wbf);
    // 2. LN1 with window permute -> bf16
    ln_kernel<true><<<TOK / 8, 256>>>(x, ln1_g, ln1_b, tmpb);
    // 3. qkv GEMM (bf16 A, fused window means)
    tgemm_kernel<0, 1, 1><<<dim3(QKC / 128, TOK / 128), 256>>>(
        tmpb, wbf + WT_QKV, qkv_b, nullptr, qkv, qw, kw, TOK, QKC, CDIM);
    // 4. router + top-4 (one block per image)
    router_kernel<<<NBATCH, 256, rsm_bytes>>>(qw, kw, tk);
    // 5. lepe depthwise conv -> tmp (fp32, image order, first writer)
    lepe_kernel<<<dim3(NPALL, 4), 256>>>(qkv, lepe_w, lepe_b, tmp);
    // 6. gathered attention (+lepe from tmp) -> bf16 hid
    attn_kernel<<<dim3(NPALL, 8), 128>>>(qkv, tk, tmp, hidb);
    // 7. wo GEMM (bf16 A) + residual -> x1
    tgemm_kernel<2, 1, 0><<<dim3(CDIM / 128, TOK / 128), 256>>>(
        hidb, wbf + WT_WO, wo_b, x, x1, nullptr, nullptr, TOK, CDIM, CDIM);
    // 8. LN2 -> bf16
    ln_kernel<false><<<TOK / 8, 256>>>(x1, ln2_g, ln2_b, tmpb);
    // 9. MLP1 + GELU -> bf16 hid
    tgemm_kernel<1, 1, 0><<<dim3(HIDC / 128, TOK / 128), 256>>>(
        tmpb, wbf + WT_W1, mlp_b1, nullptr, hidb, nullptr, nullptr, TOK, HIDC, CDIM);
    // 10. MLP2 (bf16 A) + residual -> out
    tgemm_kernel<2, 1, 0><<<dim3(CDIM / 128, TOK / 128), 256>>>(
        hidb, wbf + WT_W2, mlp_b2, x1, out, nullptr, nullptr, TOK, CDIM, HIDC);
}

// round 16
// speedup vs baseline: 1.1288x; 1.1288x over previous
#include <cuda_runtime.h>
#include <cuda_bf16.h>
#include <math.h>
#include <stdint.h>

// ---------------- problem constants ----------------
#define TOK    25088      // 8*56*56
#define NBATCH 8
#define HWDIM  56
#define CDIM   256
#define QKC    768        // qkv width
#define HIDC   1024
#define NWIN   49         // 7*7 windows per image
#define NPALL  392        // 8*49
#define WSCALE 0.0625f    // 256^-0.5

// ---------------- scratch (device globals; no allocs allowed) ----------------
__device__ __align__(256) float g_tmp256[TOK * CDIM];   // ln1(bf16) / lepe(f32) / ln2(bf16)
__device__ __align__(256) float g_qkv[TOK * QKC];
__device__ __align__(256) float g_x1[TOK * CDIM];
__device__ __align__(256) float g_hid[(size_t)TOK * HIDC / 2];  // bf16 (attn-out, then mlp hid)
__device__ float g_qwin[NPALL * CDIM];
__device__ float g_kwin[NPALL * CDIM];
__device__ int   g_topk[NPALL * 4];
__device__ __align__(256) __nv_bfloat16 g_wbf[786432];  // transposed bf16 weights

#define WT_QKV 0
#define WT_WO  196608
#define WT_W1  262144
#define WT_W2  524288

__device__ __forceinline__ uint32_t f2tf32(float x) {
    uint32_t u;
    asm("cvt.rna.tf32.f32 %0, %1;" : "=r"(u) : "f"(x));
    return u;
}
__device__ __forceinline__ float tf32f(float x) { return __uint_as_float(f2tf32(x)); }

__device__ __forceinline__ uint32_t smem_u32(const void* p) {
    uint32_t a;
    asm("{ .reg .u64 t; cvta.to.shared.u64 t, %1; cvt.u32.u64 %0, t; }" : "=r"(a) : "l"(p));
    return a;
}
__device__ __forceinline__ void cpasync16(uint32_t s, const void* g) {
    asm volatile("cp.async.cg.shared.global [%0], [%1], 16;" :: "r"(s), "l"(g) : "memory");
}
#define CP_COMMIT() asm volatile("cp.async.commit_group;" ::: "memory")
#define CP_WAIT0()  asm volatile("cp.async.wait_group 0;" ::: "memory")

// ---------------- merged weight transpose + bf16 convert (all 4 weights) --------------
__global__ void wtrans_all_kernel(const float* __restrict__ qkv_w, const float* __restrict__ wo_w,
                                  const float* __restrict__ w1, const float* __restrict__ w2,
                                  __nv_bfloat16* __restrict__ wbf) {
    __shared__ float tile[32][33];
    int b = blockIdx.x;
    const float* W; __nv_bfloat16* WT; int K, N, t;
    if (b < 192)      { W = qkv_w; WT = wbf + WT_QKV; K = CDIM; N = QKC;  t = b; }
    else if (b < 256) { W = wo_w;  WT = wbf + WT_WO;  K = CDIM; N = CDIM; t = b - 192; }
    else if (b < 512) { W = w1;    WT = wbf + WT_W1;  K = CDIM; N = HIDC; t = b - 256; }
    else              { W = w2;    WT = wbf + WT_W2;  K = HIDC; N = CDIM; t = b - 512; }
    int ktiles = K >> 5;
    int k0 = (t % ktiles) * 32, n0 = (t / ktiles) * 32;
    int tx = threadIdx.x & 31, ty = threadIdx.x >> 5;   // 32 x 8
    #pragma unroll
    for (int i = ty; i < 32; i += 8)
        tile[i][tx] = W[(size_t)(k0 + i) * N + n0 + tx];
    __syncthreads();
    #pragma unroll
    for (int i = ty; i < 32; i += 8)
        WT[(size_t)(n0 + i) * K + k0 + tx] = __float2bfloat16(tile[tx][i]);
}

// ---------------- LayerNorm (warp per token) -> bf16 out, optional window permute ----
template<bool PERM>
__global__ void ln_kernel(const float* __restrict__ X, const float* __restrict__ gam,
                          const float* __restrict__ bet, __nv_bfloat16* __restrict__ Y) {
    int warp = threadIdx.x >> 5, lane = threadIdx.x & 31;
    int t = blockIdx.x * 8 + warp;
    const float* row = X + (size_t)t * CDIM;
    float4 v0 = *(const float4*)(row + lane * 8);
    float4 v1 = *(const float4*)(row + lane * 8 + 4);
    float s  = v0.x + v0.y + v0.z + v0.w + v1.x + v1.y + v1.z + v1.w;
    float sq = v0.x*v0.x + v0.y*v0.y + v0.z*v0.z + v0.w*v0.w
             + v1.x*v1.x + v1.y*v1.y + v1.z*v1.z + v1.w*v1.w;
    #pragma unroll
    for (int o = 16; o; o >>= 1) {
        s  += __shfl_xor_sync(0xffffffffu, s, o);
        sq += __shfl_xor_sync(0xffffffffu, sq, o);
    }
    float mu  = s * (1.0f / 256.0f);
    float var = sq * (1.0f / 256.0f) - mu * mu;
    float inv = rsqrtf(var + 1e-6f);

    int orow;
    if (PERM) {
        int n = t / 3136, rem = t % 3136;
        int y = rem / 56, x = rem % 56;
        int p  = (y >> 3) * 7 + (x >> 3);
        int qi = (y & 7) * 8 + (x & 7);
        orow = (n * NWIN + p) * 64 + qi;
    } else {
        orow = t;
    }
    float4 g0 = *(const float4*)(gam + lane * 8);
    float4 g1 = *(const float4*)(gam + lane * 8 + 4);
    float4 b0 = *(const float4*)(bet + lane * 8);
    float4 b1 = *(const float4*)(bet + lane * 8 + 4);
    __nv_bfloat162 o0 = __floats2bfloat162_rn((v0.x - mu) * inv * g0.x + b0.x,
                                              (v0.y - mu) * inv * g0.y + b0.y);
    __nv_bfloat162 o1 = __floats2bfloat162_rn((v0.z - mu) * inv * g0.z + b0.z,
                                              (v0.w - mu) * inv * g0.w + b0.w);
    __nv_bfloat162 o2 = __floats2bfloat162_rn((v1.x - mu) * inv * g1.x + b1.x,
                                              (v1.y - mu) * inv * g1.y + b1.y);
    __nv_bfloat162 o3 = __floats2bfloat162_rn((v1.z - mu) * inv * g1.z + b1.z,
                                              (v1.w - mu) * inv * g1.w + b1.w);
    uint4 pk;
    pk.x = *(uint32_t*)&o0; pk.y = *(uint32_t*)&o1;
    pk.z = *(uint32_t*)&o2; pk.w = *(uint32_t*)&o3;
    *(uint4*)(Y + (size_t)orow * CDIM + lane * 8) = pk;
}

// ---------------- BF16 tensor-core GEMM 128x128x32, 256 threads, cp.async staged ------
__device__ __forceinline__ float gelu_exact(float x) {
    return 0.5f * x * (1.0f + erff(x * 0.70710678118654752440f));
}

#define WPAD 20   // row stride in 32-bit words (bf16 pairs); 16 data + 4 pad

template<int EPI, int ABF, int DOMEAN>
__global__ __launch_bounds__(256)
void tgemm_kernel(const void* __restrict__ Ain, const __nv_bfloat16* __restrict__ WT,
                  const float* __restrict__ bias, const float* __restrict__ R,
                  void* __restrict__ Cout, float* __restrict__ qw, float* __restrict__ kw,
                  int M, int N, int K) {
    __shared__ uint32_t sA[2][128 * WPAD];
    __shared__ uint32_t sB[2][128 * WPAD];

    int tid = threadIdx.x;
    int warp = tid >> 5, lane = tid & 31;
    int qr = lane >> 2, qc = lane & 3;
    int warp_m = warp >> 2, warp_n = warp & 3;   // 2 x 4
    int m0 = blockIdx.y * 128, n0 = blockIdx.x * 128;

    int aRow = tid >> 1, half = tid & 1;
    const __nv_bfloat16* Bg = WT + (size_t)(n0 + aRow) * K + half * 16;
    const __nv_bfloat16* Agb = (const __nv_bfloat16*)Ain + (size_t)(m0 + aRow) * K + half * 16;
    const float*         Agf = (const float*)Ain + (size_t)(m0 + aRow) * K + half * 16;
    uint32_t dstOff = (uint32_t)(aRow * WPAD + half * 8) * 4u;
    uint32_t sAb = smem_u32(&sA[0][0]);
    uint32_t sBb = smem_u32(&sB[0][0]);
    const uint32_t BUFB = 128u * WPAD * 4u;

    float acc[4][4][4];
    #pragma unroll
    for (int i = 0; i < 4; i++)
        #pragma unroll
        for (int j = 0; j < 4; j++)
            #pragma unroll
            for (int v = 0; v < 4; v++) acc[i][j][v] = 0.0f;

    int nch = K >> 5;

    if (ABF) {
        cpasync16(sAb + dstOff, Agb);
        cpasync16(sAb + dstOff + 16, Agb + 8);
    } else {
        float4 a0 = *(const float4*)(Agf);
        float4 a1 = *(const float4*)(Agf + 4);
        float4 a2 = *(const float4*)(Agf + 8);
        float4 a3 = *(const float4*)(Agf + 12);
        uint32_t* dA = &sA[0][aRow * WPAD + half * 8];
        __nv_bfloat162 h;
        h = __floats2bfloat162_rn(a0.x, a0.y); dA[0] = *(uint32_t*)&h;
        h = __floats2bfloat162_rn(a0.z, a0.w); dA[1] = *(uint32_t*)&h;
        h = __floats2bfloat162_rn(a1.x, a1.y); dA[2] = *(uint32_t*)&h;
        h = __floats2bfloat162_rn(a1.z, a1.w); dA[3] = *(uint32_t*)&h;
        h = __floats2bfloat162_rn(a2.x, a2.y); dA[4] = *(uint32_t*)&h;
        h = __floats2bfloat162_rn(a2.z, a2.w); dA[5] = *(uint32_t*)&h;
        h = __floats2bfloat162_rn(a3.x, a3.y); dA[6] = *(uint32_t*)&h;
        h = __floats2bfloat162_rn(a3.z, a3.w); dA[7] = *(uint32_t*)&h;
    }
    cpasync16(sBb + dstOff, Bg);
    cpasync16(sBb + dstOff + 16, Bg + 8);
    CP_COMMIT();
    CP_WAIT0();
    __syncthreads();

    for (int i = 0; i < nch; i++) {
        int b = i & 1;
        bool more = (i + 1) < nch;
        float4 na0, na1, na2, na3;
        if (more) {
            uint32_t off = (uint32_t)(b ^ 1) * BUFB + dstOff;
            if (ABF) {
                const __nv_bfloat16* ag = Agb + (size_t)(i + 1) * 32;
                cpasync16(sAb + off, ag);
                cpasync16(sAb + off + 16, ag + 8);
            } else {
                const float* ag = Agf + (size_t)(i + 1) * 32;
                na0 = *(const float4*)(ag);
                na1 = *(const float4*)(ag + 4);
                na2 = *(const float4*)(ag + 8);
                na3 = *(const float4*)(ag + 12);
            }
            const __nv_bfloat16* bg = Bg + (size_t)(i + 1) * 32;
            cpasync16(sBb + off, bg);
            cpasync16(sBb + off + 16, bg + 8);
            CP_COMMIT();
        }

        const uint32_t* Ab = sA[b];
        const uint32_t* Bb = sB[b];
        #pragma unroll
        for (int ksp = 0; ksp < 2; ksp++) {
            uint32_t af[4][4], bf[4][2];
            #pragma unroll
            for (int mt = 0; mt < 4; mt++) {
                int r = warp_m * 64 + mt * 16 + qr;
                af[mt][0] = Ab[(r)     * WPAD + ksp * 8 + qc];
                af[mt][1] = Ab[(r + 8) * WPAD + ksp * 8 + qc];
                af[mt][2] = Ab[(r)     * WPAD + ksp * 8 + qc + 4];
                af[mt][3] = Ab[(r + 8) * WPAD + ksp * 8 + qc + 4];
            }
            #pragma unroll
            for (int nt = 0; nt < 4; nt++) {
                int cn = warp_n * 32 + nt * 8 + qr;
                bf[nt][0] = Bb[cn * WPAD + ksp * 8 + qc];
                bf[nt][1] = Bb[cn * WPAD + ksp * 8 + qc + 4];
            }
            #pragma unroll
            for (int mt = 0; mt < 4; mt++)
                #pragma unroll
                for (int nt = 0; nt < 4; nt++) {
                    asm volatile(
                        "mma.sync.aligned.m16n8k16.row.col.f32.bf16.bf16.f32 "
                        "{%0,%1,%2,%3}, {%4,%5,%6,%7}, {%8,%9}, {%0,%1,%2,%3};"
                        : "+f"(acc[mt][nt][0]), "+f"(acc[mt][nt][1]),
                          "+f"(acc[mt][nt][2]), "+f"(acc[mt][nt][3])
                        : "r"(af[mt][0]), "r"(af[mt][1]), "r"(af[mt][2]), "r"(af[mt][3]),
                          "r"(bf[nt][0]), "r"(bf[nt][1]));
                }
        }

        if (more) {
            if (!ABF) {
                uint32_t* dA = &sA[b ^ 1][aRow * WPAD + half * 8];
                __nv_bfloat162 h;
                h = __floats2bfloat162_rn(na0.x, na0.y); dA[0] = *(uint32_t*)&h;
                h = __floats2bfloat162_rn(na0.z, na0.w); dA[1] = *(uint32_t*)&h;
                h = __floats2bfloat162_rn(na1.x, na1.y); dA[2] = *(uint32_t*)&h;
                h = __floats2bfloat162_rn(na1.z, na1.w); dA[3] = *(uint32_t*)&h;
                h = __floats2bfloat162_rn(na2.x, na2.y); dA[4] = *(uint32_t*)&h;
                h = __floats2bfloat162_rn(na2.z, na2.w); dA[5] = *(uint32_t*)&h;
                h = __floats2bfloat162_rn(na3.x, na3.y); dA[6] = *(uint32_t*)&h;
                h = __floats2bfloat162_rn(na3.z, na3.w); dA[7] = *(uint32_t*)&h;
            }
            CP_WAIT0();
        }
        __syncthreads();
    }

    // ---- epilogue ----
    #pragma unroll
    for (int nt = 0; nt < 4; nt++) {
        int col = n0 + warp_n * 32 + nt * 8 + qc * 2;
        float bx = bias[col], by = bias[col + 1];
        float cs0 = 0.f, cs1 = 0.f;
        #pragma unroll
        for (int mt = 0; mt < 4; mt++) {
            int row = m0 + warp_m * 64 + mt * 16 + qr;
            float v0 = acc[mt][nt][0] + bx;
            float v1 = acc[mt][nt][1] + by;
            float v2 = acc[mt][nt][2] + bx;
            float v3 = acc[mt][nt][3] + by;
            if (DOMEAN) { cs0 += v0 + v2; cs1 += v1 + v3; }
            if (EPI == 1) {
                __nv_bfloat162 ha = __floats2bfloat162_rn(gelu_exact(v0), gelu_exact(v1));
                __nv_bfloat162 hb = __floats2bfloat162_rn(gelu_exact(v2), gelu_exact(v3));
                __nv_bfloat16* cb = (__nv_bfloat16*)Cout;
                *(__nv_bfloat162*)(cb + (size_t)row * N + col)       = ha;
                *(__nv_bfloat162*)(cb + (size_t)(row + 8) * N + col) = hb;
            } else {
                if (EPI == 2) {
                    float2 ra = *(const float2*)(R + (size_t)row * N + col);
                    float2 rb = *(const float2*)(R + (size_t)(row + 8) * N + col);
                    v0 += ra.x; v1 += ra.y; v2 += rb.x; v3 += rb.y;
                }
                float* cf = (float*)Cout;
                float2 oa; oa.x = v0; oa.y = v1;
                float2 ob; ob.x = v2; ob.y = v3;
                *(float2*)(cf + (size_t)row * N + col)       = oa;
                *(float2*)(cf + (size_t)(row + 8) * N + col) = ob;
            }
        }
        if (DOMEAN && n0 < 512) {
            #pragma unroll
            for (int o = 4; o <= 16; o <<= 1) {
                cs0 += __shfl_xor_sync(0xffffffffu, cs0, o);
                cs1 += __shfl_xor_sync(0xffffffffu, cs1, o);
            }
            if (qr == 0) {
                int win = blockIdx.y * 2 + warp_m;
                float mv0 = cs0 * (1.0f / 64.0f);
                float mv1 = cs1 * (1.0f / 64.0f);
                if (col < 256) {
                    qw[win * CDIM + col]     = mv0;
                    qw[win * CDIM + col + 1] = mv1;
                } else {
                    kw[win * CDIM + col - 256] = mv0;
                    kw[win * CDIM + col - 255] = mv1;
                }
            }
        }
    }
}

// ---------------- fused wo GEMM (128x256 tile) + residual + LayerNorm2 ---------------
// A = attn-out bf16 [M][256]; B = wo^T bf16 [256][256]; writes x1 fp32 AND ln2(x1) bf16
#define WOSM (2 * (128 * WPAD + 256 * WPAD) * 4)   // 61440 bytes dynamic

__global__ __launch_bounds__(256)
void wo_ln_kernel(const __nv_bfloat16* __restrict__ Ain, const __nv_bfloat16* __restrict__ WT,
                  const float* __restrict__ bias, const float* __restrict__ R,
                  float* __restrict__ X1, const float* __restrict__ gam,
                  const float* __restrict__ bet, __nv_bfloat16* __restrict__ Yb) {
    extern __shared__ uint32_t wsm[];
    __shared__ float lnred[128][4][2];

    const int K = 256, N = 256;
    int tid = threadIdx.x;
    int warp = tid >> 5, lane = tid & 31;
    int qr = lane >> 2, qc = lane & 3;
    int warp_m = warp >> 2, warp_n = warp & 3;   // 2(m) x 4(n), warp_n covers 64 cols
    int m0 = blockIdx.x * 128;

    int aRow = tid >> 1, half = tid & 1;
    const __nv_bfloat16* Ag = Ain + (size_t)(m0 + aRow) * K + half * 16;
    const __nv_bfloat16* Bg = WT + (size_t)tid * K;   // B row = tid (0..255)
    uint32_t sbase = smem_u32(wsm);
    uint32_t aOff = (uint32_t)(aRow * WPAD + half * 8) * 4u;
    uint32_t bOff = (uint32_t)(tid * WPAD) * 4u;
    const uint32_t ABUF = 128u * WPAD * 4u;
    const uint32_t BBASE = 2u * ABUF;
    const uint32_t BBUF = 256u * WPAD * 4u;

    float acc[4][8][4];
    #pragma unroll
    for (int i = 0; i < 4; i++)
        #pragma unroll
        for (int j = 0; j < 8; j++)
            #pragma unroll
            for (int v = 0; v < 4; v++) acc[i][j][v] = 0.0f;

    const int nch = K >> 5;   // 8

    // prologue: chunk 0 -> buffer 0
    cpasync16(sbase + aOff, Ag);
    cpasync16(sbase + aOff + 16, Ag + 8);
    cpasync16(sbase + BBASE + bOff, Bg);
    cpasync16(sbase + BBASE + bOff + 16, Bg + 8);
    cpasync16(sbase + BBASE + bOff + 32, Bg + 16);
    cpasync16(sbase + BBASE + bOff + 48, Bg + 24);
    CP_COMMIT();
    CP_WAIT0();
    __syncthreads();

    for (int i = 0; i < nch; i++) {
        int b = i & 1;
        bool more = (i + 1) < nch;
        if (more) {
            uint32_t aoff2 = (uint32_t)(b ^ 1) * ABUF + aOff;
            uint32_t boff2 = BBASE + (uint32_t)(b ^ 1) * BBUF + bOff;
            const __nv_bfloat16* ag = Ag + (size_t)(i + 1) * 32;
            const __nv_bfloat16* bg = Bg + (size_t)(i + 1) * 32;
            cpasync16(sbase + aoff2, ag);
            cpasync16(sbase + aoff2 + 16, ag + 8);
            cpasync16(sbase + boff2, bg);
            cpasync16(sbase + boff2 + 16, bg + 8);
            cpasync16(sbase + boff2 + 32, bg + 16);
            cpasync16(sbase + boff2 + 48, bg + 24);
            CP_COMMIT();
        }

        const uint32_t* Ab = wsm + (size_t)b * 128 * WPAD;
        const uint32_t* Bb = wsm + 2 * 128 * WPAD + (size_t)b * 256 * WPAD;
        #pragma unroll
        for (int ksp = 0; ksp < 2; ksp++) {
            uint32_t af[4][4], bf[8][2];
            #pragma unroll
            for (int mt = 0; mt < 4; mt++) {
                int r = warp_m * 64 + mt * 16 + qr;
                af[mt][0] = Ab[(r)     * WPAD + ksp * 8 + qc];
                af[mt][1] = Ab[(r + 8) * WPAD + ksp * 8 + qc];
                af[mt][2] = Ab[(r)     * WPAD + ksp * 8 + qc + 4];
                af[mt][3] = Ab[(r + 8) * WPAD + ksp * 8 + qc + 4];
            }
            #pragma unroll
            for (int nt = 0; nt < 8; nt++) {
                int cn = warp_n * 64 + nt * 8 + qr;
                bf[nt][0] = Bb[cn * WPAD + ksp * 8 + qc];
                bf[nt][1] = Bb[cn * WPAD + ksp * 8 + qc + 4];
            }
            #pragma unroll
            for (int mt = 0; mt < 4; mt++)
                #pragma unroll
                for (int nt = 0; nt < 8; nt++) {
                    asm volatile(
                        "mma.sync.aligned.m16n8k16.row.col.f32.bf16.bf16.f32 "
                        "{%0,%1,%2,%3}, {%4,%5,%6,%7}, {%8,%9}, {%0,%1,%2,%3};"
                        : "+f"(acc[mt][nt][0]), "+f"(acc[mt][nt][1]),
                          "+f"(acc[mt][nt][2]), "+f"(acc[mt][nt][3])
                        : "r"(af[mt][0]), "r"(af[mt][1]), "r"(af[mt][2]), "r"(af[mt][3]),
                          "r"(bf[nt][0]), "r"(bf[nt][1]));
                }
        }

        if (more) CP_WAIT0();
        __syncthreads();
    }

    // ---- pass 1: x1 = acc + bias + residual; write fp32; accumulate LN stats ----
    float sum0[4] = {0.f, 0.f, 0.f, 0.f}, sq0[4] = {0.f, 0.f, 0.f, 0.f};
    float sum1[4] = {0.f, 0.f, 0.f, 0.f}, sq1[4] = {0.f, 0.f, 0.f, 0.f};
    #pragma unroll
    for (int nt = 0; nt < 8; nt++) {
        int col = warp_n * 64 + nt * 8 + qc * 2;
        float2 bv = *(const float2*)(bias + col);
        #pragma unroll
        for (int mt = 0; mt < 4; mt++) {
            int row = m0 + warp_m * 64 + mt * 16 + qr;
            float v0 = acc[mt][nt][0] + bv.x;
            float v1 = acc[mt][nt][1] + bv.y;
            float v2 = acc[mt][nt][2] + bv.x;
            float v3 = acc[mt][nt][3] + bv.y;
            float2 ra = *(const float2*)(R + (size_t)row * N + col);
            float2 rb = *(const float2*)(R + (size_t)(row + 8) * N + col);
            v0 += ra.x; v1 += ra.y; v2 += rb.x; v3 += rb.y;
            float2 oa; oa.x = v0; oa.y = v1;
            float2 ob; ob.x = v2; ob.y = v3;
            *(float2*)(X1 + (size_t)row * N + col)       = oa;
            *(float2*)(X1 + (size_t)(row + 8) * N + col) = ob;
            sum0[mt] += v0 + v1; sq0[mt] += v0 * v0 + v1 * v1;
            sum1[mt] += v2 + v3; sq1[mt] += v2 * v2 + v3 * v3;
            acc[mt][nt][0] = v0; acc[mt][nt][1] = v1;
            acc[mt][nt][2] = v2; acc[mt][nt][3] = v3;
        }
    }
    // quad reduce (over qc) -> per (row, warp_n) sums of 64 cols
    #pragma unroll
    for (int mt = 0; mt < 4; mt++) {
        #pragma unroll
        for (int o = 1; o <= 2; o <<= 1) {
            sum0[mt] += __shfl_xor_sync(0xffffffffu, sum0[mt], o);
            sq0[mt]  += __shfl_xor_sync(0xffffffffu, sq0[mt], o);
            sum1[mt] += __shfl_xor_sync(0xffffffffu, sum1[mt], o);
            sq1[mt]  += __shfl_xor_sync(0xffffffffu, sq1[mt], o);
        }
    }
    if (qc == 0) {
        #pragma unroll
        for (int mt = 0; mt < 4; mt++) {
            int rl = warp_m * 64 + mt * 16 + qr;
            lnred[rl][warp_n][0]     = sum0[mt];
            lnred[rl][warp_n][1]     = sq0[mt];
            lnred[rl + 8][warp_n][0] = sum1[mt];
            lnred[rl + 8][warp_n][1] = sq1[mt];
        }
    }
    __syncthreads();

    float mu0[4], iv0[4], mu1[4], iv1[4];
    #pragma unroll
    for (int mt = 0; mt < 4; mt++) {
        int rl = warp_m * 64 + mt * 16 + qr;
        float s = lnred[rl][0][0] + lnred[rl][1][0] + lnred[rl][2][0] + lnred[rl][3][0];
        float q = lnred[rl][0][1] + lnred[rl][1][1] + lnred[rl][2][1] + lnred[rl][3][1];
        float m = s * (1.0f / 256.0f);
        mu0[mt] = m;
        iv0[mt] = rsqrtf(q * (1.0f / 256.0f) - m * m + 1e-6f);
        s = lnred[rl + 8][0][0] + lnred[rl + 8][1][0] + lnred[rl + 8][2][0] + lnred[rl + 8][3][0];
        q = lnred[rl + 8][0][1] + lnred[rl + 8][1][1] + lnred[rl + 8][2][1] + lnred[rl + 8][3][1];
        m = s * (1.0f / 256.0f);
        mu1[mt] = m;
        iv1[mt] = rsqrtf(q * (1.0f / 256.0f) - m * m + 1e-6f);
    }

    // ---- pass 2: y = (x1 - mu) * inv * gamma + beta -> bf16 ----
    #pragma unroll
    for (int nt = 0; nt < 8; nt++) {
        int col = warp_n * 64 + nt * 8 + qc * 2;
        float2 gv = *(const float2*)(gam + col);
        float2 bv = *(const float2*)(bet + col);
        #pragma unroll
        for (int mt = 0; mt < 4; mt++) {
            int row = m0 + warp_m * 64 + mt * 16 + qr;
            float y0 = (acc[mt][nt][0] - mu0[mt]) * iv0[mt] * gv.x + bv.x;
            float y1 = (acc[mt][nt][1] - mu0[mt]) * iv0[mt] * gv.y + bv.y;
            float y2 = (acc[mt][nt][2] - mu1[mt]) * iv1[mt] * gv.x + bv.x;
            float y3 = (acc[mt][nt][3] - mu1[mt]) * iv1[mt] * gv.y + bv.y;
            __nv_bfloat162 ha = __floats2bfloat162_rn(y0, y1);
            __nv_bfloat162 hb = __floats2bfloat162_rn(y2, y3);
            *(__nv_bfloat162*)(Yb + (size_t)row * N + col)       = ha;
            *(__nv_bfloat162*)(Yb + (size_t)(row + 8) * N + col) = hb;
        }
    }
}

// ---------------- router: warp-per-logit, coalesced + shfl reduce (R12 proven) -------
__global__ void router_kernel(const float* __restrict__ qw, const float* __restrict__ kw,
                              int* __restrict__ topk) {
    int np = blockIdx.x;
    int n = np / NWIN;
    int tid = threadIdx.x;
    int warp = tid >> 5, lane = tid & 31;
    __shared__ float qs[CDIM];
    __shared__ float lg[64];
    qs[tid] = qw[np * CDIM + tid] * WSCALE;
    __syncthreads();
    for (int q = warp; q < NWIN; q += 8) {
        const float* kr = kw + (size_t)(n * NWIN + q) * CDIM;
        float s = 0.f;
        #pragma unroll
        for (int h = 0; h < 2; h++) {
            float4 kv = ((const float4*)kr)[h * 32 + lane];
            float4 qv = ((const float4*)qs)[h * 32 + lane];
            s += kv.x * qv.x + kv.y * qv.y + kv.z * qv.z + kv.w * qv.w;
        }
        #pragma unroll
        for (int o = 16; o; o >>= 1) s += __shfl_xor_sync(0xffffffffu, s, o);
        if (lane == 0) lg[q] = s;
    }
    __syncthreads();
    if (tid == 0) {
        bool used[NWIN];
        #pragma unroll
        for (int i = 0; i < NWIN; i++) used[i] = false;
        for (int r = 0; r < 4; r++) {
            float best = -1e30f; int bi = 0;
            for (int q = 0; q < NWIN; q++)
                if (!used[q] && lg[q] > best) { best = lg[q]; bi = q; }
            used[bi] = true;
            topk[np * 4 + r] = bi;
        }
    }
}

// ---------------- 5x5 depthwise lepe, smem-tiled, WRITES O (first writer) ------------
__global__ __launch_bounds__(256)
void lepe_kernel(const float* __restrict__ QKV, const float* __restrict__ W,
                 const float* __restrict__ B, float* __restrict__ O) {
    __shared__ float sv[144][64];
    __shared__ float sw[25][64];
    int np = blockIdx.x, cg = blockIdx.y;
    int n = np / NWIN, p = np % NWIN;
    int jj = p / 7, ii = p % 7;
    int tid = threadIdx.x;

    for (int i = tid; i < 1600; i += 256)
        sw[i / 64][i % 64] = W[(i / 64) * CDIM + cg * 64 + (i % 64)];

    for (int i = tid; i < 2304; i += 256) {
        int pos = i >> 4, c4 = i & 15;
        int yy = jj * 8 + (pos / 12) - 2;
        int xx = ii * 8 + (pos % 12) - 2;
        float4 v = make_float4(0.f, 0.f, 0.f, 0.f);
        if (yy >= 0 && yy < HWDIM && xx >= 0 && xx < HWDIM) {
            int pp = (yy >> 3) * 7 + (xx >> 3);
            int qi = (yy & 7) * 8 + (xx & 7);
            const float* src = QKV + ((size_t)(n * NWIN + pp) * 64 + qi) * QKC + 512 + cg * 64;
            v = *(const float4*)(src + c4 * 4);
        }
        *(float4*)&sv[pos][c4 * 4] = v;
    }
    __syncthreads();

    int c = tid & 63, pp0 = tid >> 6;
    float wr[25];
    #pragma unroll
    for (int t5 = 0; t5 < 25; t5++) wr[t5] = sw[t5][c];
    float bias = B[cg * 64 + c];

    #pragma unroll
    for (int hi = 0; hi < 2; hi++) {
        int hh = pp0 + hi * 4;
        #pragma unroll
        for (int ww = 0; ww < 8; ww++) {
            float acc = bias;
            #pragma unroll
            for (int dy = 0; dy < 5; dy++)
                #pragma unroll
                for (int dx = 0; dx < 5; dx++)
                    acc += sv[(hh + dy) * 12 + (ww + dx)][c] * wr[dy * 5 + dx];
            int y = jj * 8 + hh, x = ii * 8 + ww;
            int t = (n * HWDIM + y) * HWDIM + x;
            O[(size_t)t * CDIM + cg * 64 + c] = acc;
        }
    }
}

// ---------------- tensor-core gathered attention (R12 proven: 64 thr, 2 warps) -------
#define KS_STRIDE 36
#define VS_STRIDE 40
#define PS_STRIDE 68
__global__ __launch_bounds__(64)
void attn_kernel(const float* __restrict__ QKV, const int* __restrict__ topk,
                 const float* __restrict__ L, __nv_bfloat16* __restrict__ O) {
    __shared__ float ks[64][KS_STRIDE];
    __shared__ float vs[64][VS_STRIDE];
    __shared__ float ps[64][PS_STRIDE];   // Q stage (32 cols), then per-warp P (64 cols)

    int np = blockIdx.x, mh = blockIdx.y;
    int n = np / NWIN, p = np % NWIN;
    int tid = threadIdx.x, warp = tid >> 5, lane = tid & 31;
    int qr = lane >> 2, qc = lane & 3;

    const float* qbase = QKV + (size_t)np * 64 * QKC + mh * 32;
    for (int i = tid; i < 512; i += 64) {
        int r = i >> 3, c = (i & 7) * 4;
        float4 v = *(const float4*)(qbase + (size_t)r * QKC + c);
        ps[r][c + 0] = tf32f(v.x * WSCALE);
        ps[r][c + 1] = tf32f(v.y * WSCALE);
        ps[r][c + 2] = tf32f(v.z * WSCALE);
        ps[r][c + 3] = tf32f(v.w * WSCALE);
    }
    __syncthreads();

    uint32_t qf[2][4][4];
    #pragma unroll
    for (int mt = 0; mt < 2; mt++) {
        int r = warp * 32 + mt * 16 + qr;
        #pragma unroll
        for (int kk = 0; kk < 4; kk++) {
            qf[mt][kk][0] = __float_as_uint(ps[r][kk * 8 + qc]);
            qf[mt][kk][1] = __float_as_uint(ps[r + 8][kk * 8 + qc]);
            qf[mt][kk][2] = __float_as_uint(ps[r][kk * 8 + qc + 4]);
            qf[mt][kk][3] = __float_as_uint(ps[r + 8][kk * 8 + qc + 4]);
        }
    }
    __syncthreads();   // ps reused for P below

    float mrun[4] = {-1e30f, -1e30f, -1e30f, -1e30f};
    float lrun[4] = {0.f, 0.f, 0.f, 0.f};
    float oacc[2][4][4];
    #pragma unroll
    for (int mt = 0; mt < 2; mt++)
        #pragma unroll
        for (int nt = 0; nt < 4; nt++)
            #pragma unroll
            for (int v = 0; v < 4; v++) oacc[mt][nt][v] = 0.f;

    for (int t4 = 0; t4 < 4; t4++) {
        int rwin = topk[np * 4 + t4];
        const float* kb = QKV + (size_t)(n * NWIN + rwin) * 64 * QKC + 256 + mh * 32;
        for (int i = tid; i < 512; i += 64) {
            int r = i >> 3, c = (i & 7) * 4;
            float4 kv = *(const float4*)(kb + (size_t)r * QKC + c);
            ks[r][c + 0] = tf32f(kv.x); ks[r][c + 1] = tf32f(kv.y);
            ks[r][c + 2] = tf32f(kv.z); ks[r][c + 3] = tf32f(kv.w);
            float4 vv = *(const float4*)(kb + (size_t)r * QKC + 256 + c);
            vs[r][c + 0] = tf32f(vv.x); vs[r][c + 1] = tf32f(vv.y);
            vs[r][c + 2] = tf32f(vv.z); vs[r][c + 3] = tf32f(vv.w);
        }
        __syncthreads();

        float sacc[2][8][4];
        #pragma unroll
        for (int mt = 0; mt < 2; mt++)
            #pragma unroll
            for (int nt = 0; nt < 8; nt++)
                #pragma unroll
                for (int v = 0; v < 4; v++) sacc[mt][nt][v] = 0.f;

        #pragma unroll
        for (int kk = 0; kk < 4; kk++) {
            uint32_t bf[8][2];
            #pragma unroll
            for (int nt = 0; nt < 8; nt++) {
                bf[nt][0] = __float_as_uint(ks[nt * 8 + qr][kk * 8 + qc]);
                bf[nt][1] = __float_as_uint(ks[nt * 8 + qr][kk * 8 + qc + 4]);
            }
            #pragma unroll
            for (int mt = 0; mt < 2; mt++)
                #pragma unroll
                for (int nt = 0; nt < 8; nt++) {
                    asm volatile(
                        "mma.sync.aligned.m16n8k8.row.col.f32.tf32.tf32.f32 "
                        "{%0,%1,%2,%3}, {%4,%5,%6,%7}, {%8,%9}, {%0,%1,%2,%3};"
                        : "+f"(sacc[mt][nt][0]), "+f"(sacc[mt][nt][1]),
                          "+f"(sacc[mt][nt][2]), "+f"(sacc[mt][nt][3])
                        : "r"(qf[mt][kk][0]), "r"(qf[mt][kk][1]),
                          "r"(qf[mt][kk][2]), "r"(qf[mt][kk][3]),
                          "r"(bf[nt][0]), "r"(bf[nt][1]));
                }
        }

        float rmax[4] = {-1e30f, -1e30f, -1e30f, -1e30f};
        #pragma unroll
        for (int mt = 0; mt < 2; mt++)
            #pragma unroll
            for (int nt = 0; nt < 8; nt++) {
                rmax[mt * 2 + 0] = fmaxf(rmax[mt * 2 + 0], fmaxf(sacc[mt][nt][0], sacc[mt][nt][1]));
                rmax[mt * 2 + 1] = fmaxf(rmax[mt * 2 + 1], fmaxf(sacc[mt][nt][2], sacc[mt][nt][3]));
            }
        #pragma unroll
        for (int g = 0; g < 4; g++) {
            rmax[g] = fmaxf(rmax[g], __shfl_xor_sync(0xffffffffu, rmax[g], 1));
            rmax[g] = fmaxf(rmax[g], __shfl_xor_sync(0xffffffffu, rmax[g], 2));
        }
        float corr[4], mnew[4];
        #pragma unroll
        for (int g = 0; g < 4; g++) {
            mnew[g] = fmaxf(mrun[g], rmax[g]);
            corr[g] = __expf(mrun[g] - mnew[g]);
            lrun[g] *= corr[g];
            mrun[g] = mnew[g];
        }
        #pragma unroll
        for (int mt = 0; mt < 2; mt++)
            #pragma unroll
            for (int nt = 0; nt < 4; nt++) {
                oacc[mt][nt][0] *= corr[mt * 2 + 0];
                oacc[mt][nt][1] *= corr[mt * 2 + 0];
                oacc[mt][nt][2] *= corr[mt * 2 + 1];
                oacc[mt][nt][3] *= corr[mt * 2 + 1];
            }
        float psum[4] = {0.f, 0.f, 0.f, 0.f};
        #pragma unroll
        for (int mt = 0; mt < 2; mt++) {
            int r0 = warp * 32 + mt * 16 + qr;
            #pragma unroll
            for (int nt = 0; nt < 8; nt++) {
                float p0 = __expf(sacc[mt][nt][0] - mnew[mt * 2 + 0]);
                float p1 = __expf(sacc[mt][nt][1] - mnew[mt * 2 + 0]);
                float p2 = __expf(sacc[mt][nt][2] - mnew[mt * 2 + 1]);
                float p3 = __expf(sacc[mt][nt][3] - mnew[mt * 2 + 1]);
                psum[mt * 2 + 0] += p0 + p1;
                psum[mt * 2 + 1] += p2 + p3;
                float2 w0; w0.x = tf32f(p0); w0.y = tf32f(p1);
                float2 w1; w1.x = tf32f(p2); w1.y = tf32f(p3);
                *(float2*)&ps[r0][nt * 8 + qc * 2]     = w0;
                *(float2*)&ps[r0 + 8][nt * 8 + qc * 2] = w1;
            }
        }
        #pragma unroll
        for (int g = 0; g < 4; g++) {
            psum[g] += __shfl_xor_sync(0xffffffffu, psum[g], 1);
            psum[g] += __shfl_xor_sync(0xffffffffu, psum[g], 2);
            lrun[g] += psum[g];
        }
        __syncwarp();

        #pragma unroll
        for (int kt = 0; kt < 8; kt++) {
            uint32_t af[2][4], bf[4][2];
            #pragma unroll
            for (int mt = 0; mt < 2; mt++) {
                int r = warp * 32 + mt * 16 + qr;
                af[mt][0] = __float_as_uint(ps[r][kt * 8 + qc]);
                af[mt][1] = __float_as_uint(ps[r + 8][kt * 8 + qc]);
                af[mt][2] = __float_as_uint(ps[r][kt * 8 + qc + 4]);
                af[mt][3] = __float_as_uint(ps[r + 8][kt * 8 + qc + 4]);
            }
            #pragma unroll
            for (int nt = 0; nt < 4; nt++) {
                bf[nt][0] = __float_as_uint(vs[kt * 8 + qc][nt * 8 + qr]);
                bf[nt][1] = __float_as_uint(vs[kt * 8 + qc + 4][nt * 8 + qr]);
            }
            #pragma unroll
            for (int mt = 0; mt < 2; mt++)
                #pragma unroll
                for (int nt = 0; nt < 4; nt++) {
                    asm volatile(
                        "mma.sync.aligned.m16n8k8.row.col.f32.tf32.tf32.f32 "
                        "{%0,%1,%2,%3}, {%4,%5,%6,%7}, {%8,%9}, {%0,%1,%2,%3};"
                        : "+f"(oacc[mt][nt][0]), "+f"(oacc[mt][nt][1]),
                          "+f"(oacc[mt][nt][2]), "+f"(oacc[mt][nt][3])
                        : "r"(af[mt][0]), "r"(af[mt][1]), "r"(af[mt][2]), "r"(af[mt][3]),
                          "r"(bf[nt][0]), "r"(bf[nt][1]));
                }
        }
        __syncthreads();
    }

    // ---- finalize: /l, add lepe value (fp32), write bf16 image-order output ----
    float linv[4];
    #pragma unroll
    for (int g = 0; g < 4; g++) linv[g] = 1.0f / lrun[g];

    int jj = p / 7, ii = p % 7;
    #pragma unroll
    for (int mt = 0; mt < 2; mt++) {
        #pragma unroll
        for (int half = 0; half < 2; half++) {
            int q = warp * 32 + mt * 16 + qr + half * 8;
            int y = jj * 8 + (q >> 3), x = ii * 8 + (q & 7);
            size_t base = ((size_t)(n * HWDIM + y) * HWDIM + x) * CDIM + mh * 32;
            const float* lrow = L + base;
            __nv_bfloat16* orow = O + base;
            float li = linv[mt * 2 + half];
            #pragma unroll
            for (int nt = 0; nt < 4; nt++) {
                float2 lv = *(const float2*)(lrow + nt * 8 + qc * 2);
                float a0 = oacc[mt][nt][half * 2 + 0] * li + lv.x;
                float a1 = oacc[mt][nt][half * 2 + 1] * li + lv.y;
                __nv_bfloat162 ov = __floats2bfloat162_rn(a0, a1);
                *(__nv_bfloat162*)(orow + nt * 8 + qc * 2) = ov;
            }
        }
    }
}

// ---------------- host launch ----------------
extern "C" void kernel_launch(void* const* d_in, const int* in_sizes, int n_in,
                              void* d_out, int out_size) {
    const float* x      = (const float*)d_in[0];
    const float* ln1_g  = (const float*)d_in[1];
    const float* ln1_b  = (const float*)d_in[2];
    const float* qkv_w  = (const float*)d_in[3];
    const float* qkv_b  = (const float*)d_in[4];
    const float* lepe_w = (const float*)d_in[5];
    const float* lepe_b = (const float*)d_in[6];
    const float* wo_w   = (const float*)d_in[7];
    const float* wo_b   = (const float*)d_in[8];
    const float* ln2_g  = (const float*)d_in[9];
    const float* ln2_b  = (const float*)d_in[10];
    const float* mlp_w1 = (const float*)d_in[11];
    const float* mlp_b1 = (const float*)d_in[12];
    const float* mlp_w2 = (const float*)d_in[13];
    const float* mlp_b2 = (const float*)d_in[14];
    float* out = (float*)d_out;

    float *tmp, *qkv, *x1, *hid, *qw, *kw;
    int* tk;
    __nv_bfloat16* wbf;
    cudaGetSymbolAddress((void**)&tmp, g_tmp256);
    cudaGetSymbolAddress((void**)&qkv, g_qkv);
    cudaGetSymbolAddress((void**)&x1,  g_x1);
    cudaGetSymbolAddress((void**)&hid, g_hid);
    cudaGetSymbolAddress((void**)&qw,  g_qwin);
    cudaGetSymbolAddress((void**)&kw,  g_kwin);
    cudaGetSymbolAddress((void**)&tk,  g_topk);
    cudaGetSymbolAddress((void**)&wbf, g_wbf);
    __nv_bfloat16* tmpb = (__nv_bfloat16*)tmp;
    __nv_bfloat16* hidb = (__nv_bfloat16*)hid;

    cudaFuncSetAttribute(wo_ln_kernel, cudaFuncAttributeMaxDynamicSharedMemorySize, WOSM);

    // 1. transpose + bf16-convert ALL weights (single launch)
    wtrans_all_kernel<<<768, 256>>>(qkv_w, wo_w, mlp_w1, mlp_w2, wbf);
    // 2. LN1 with window permute -> bf16
    ln_kernel<true><<<TOK / 8, 256>>>(x, ln1_g, ln1_b, tmpb);
    // 3. qkv GEMM (bf16 A, fused window means)
    tgemm_kernel<0, 1, 1><<<dim3(QKC / 128, TOK / 128), 256>>>(
        tmpb, wbf + WT_QKV, qkv_b, nullptr, qkv, qw, kw, TOK, QKC, CDIM);
    // 4. router + top-4
    router_kernel<<<NPALL, 256>>>(qw, kw, tk);
    // 5. lepe depthwise conv -> tmp (fp32, image order, first writer)
    lepe_kernel<<<dim3(NPALL, 4), 256>>>(qkv, lepe_w, lepe_b, tmp);
    // 6. gathered attention (+lepe from tmp) -> bf16 hid
    attn_kernel<<<dim3(NPALL, 8), 64>>>(qkv, tk, tmp, hidb);
    // 7. fused wo GEMM + residual + LN2: writes x1 (fp32) AND ln2 -> bf16 tmp
    wo_ln_kernel<<<TOK / 128, 256, WOSM>>>(hidb, wbf + WT_WO, wo_b, x, x1,
                                           ln2_g, ln2_b, tmpb);
    // 8. MLP1 + GELU -> bf16 hid
    tgemm_kernel<1, 1, 0><<<dim3(HIDC / 128, TOK / 128), 256>>>(
        tmpb, wbf + WT_W1, mlp_b1, nullptr, hidb, nullptr, nullptr, TOK, HIDC, CDIM);
    // 9. MLP2 (bf16 A) + residual -> out
    tgemm_kernel<2, 1, 0><<<dim3(CDIM / 128, TOK / 128), 256>>>(
        hidb, wbf + WT_W2, mlp_b2, x1, out, nullptr, nullptr, TOK, CDIM, HIDC);
}